// round 16
// baseline (speedup 1.0000x reference)
#include <cuda_runtime.h>
#include <cuda_bf16.h>
#include <cstdint>
#include <cmath>

// ---------------------------------------------------------------------------
// DecoderRNN, persistent-GRU, L1-traffic-minimized:
//  * 4 warps/CTA (128 thr), warp tile 64x48 -> LDSM redundancy (A x2, B x2)
//  * h stored once, fp32, in g_Hall (logits tf32 mma truncates in-HW);
//    fp32 ping-pong buffer deleted
//  * token table GI2[v][2048] = gi_r+bhh_r | gi_z+bhh_z | gi_n | bhh_n
//  * per-m-block 16-CTA barriers; split A/B cp.async.bulk rings (B crosses
//    the barrier); ldmatrix.x4 fragments; mma m16n8k16 bf16; fp32 gates
//  * ONE batched tf32 logits GEMM + fused log_softmax at the end
// Output: [160*2048*128 log_probs fp32][2048*512 final hidden fp32]
// ---------------------------------------------------------------------------

#define HID   512
#define VOC   128
#define EMBD  64
#define BSZ   2048
#define TLEN  160
#define G3    1536

#define ABLK   (128 * 40)            // 10240 B per A tile
#define BBLK   (96 * 40)             //  7680 B per B tile
#define A_RING (4 * 10240)
#define B_RING (4 * 7680)
#define GRU_SMEM (A_RING + B_RING)   // 71680 B (2 CTAs/SM)

// logits tf32 tiling (proven path, unchanged)
#define AS_LD  36
#define BS2_LD 136
#define EP_LD  132
#define SBUF2  (128 * AS_LD + 32 * BS2_LD)

// Static scratch
__device__ __nv_bfloat16 g_Wst[16 * 16 * BBLK];          // W_hh bf16, tiled
__device__ float g_WoT [HID * VOC];                      // W_out^T tf32 [k][v]
__device__ float g_GI2 [VOC * 2048];                     // fused token table
__device__ float g_Hall[(size_t)(TLEN + 1) * BSZ * HID]; // fp32 hidden history
__device__ __nv_bfloat16 g_Hab[(size_t)(TLEN + 1) * 256 * ABLK]; // bf16 tiled hidden
__device__ unsigned g_mbar[16 * 32];                     // per-m barriers, 128B apart

__device__ __forceinline__ float tf32r(float x) {
    unsigned u;
    asm("cvt.rna.tf32.f32 %0, %1;" : "=r"(u) : "f"(x));
    return __uint_as_float(u);
}
__device__ __forceinline__ uint32_t smem_u32(const void* p) {
    uint32_t a;
    asm("{ .reg .u64 t; cvta.to.shared.u64 t, %1; cvt.u32.u64 %0, t; }" : "=r"(a) : "l"(p));
    return a;
}
__device__ __forceinline__ void cpa16(const void* dst, const void* src) {
    unsigned d = (unsigned)__cvta_generic_to_shared(dst);
    asm volatile("cp.async.cg.shared.global [%0], [%1], 16;" :: "r"(d), "l"(src));
}
#define CP_COMMIT() asm volatile("cp.async.commit_group;")
#define CP_WAIT(n)  asm volatile("cp.async.wait_group %0;" :: "n"(n))

__device__ __forceinline__ void mb_init(uint32_t a, uint32_t cnt) {
    asm volatile("mbarrier.init.shared.b64 [%0], %1;" :: "r"(a), "r"(cnt) : "memory");
}
__device__ __forceinline__ void mb_wait(uint32_t a, uint32_t parity) {
    asm volatile(
        "{\n\t.reg .pred P;\n\t"
        "W_%=:\n\t"
        "mbarrier.try_wait.parity.acquire.cta.shared::cta.b64 P, [%0], %1, 0x989680;\n\t"
        "@P bra.uni D_%=;\n\t"
        "bra.uni W_%=;\n\t"
        "D_%=:\n\t}"
        :: "r"(a), "r"(parity) : "memory");
}
__device__ __forceinline__ void mb_expect(uint32_t a, uint32_t bytes) {
    asm volatile("mbarrier.arrive.expect_tx.shared.b64 _, [%0], %1;"
                 :: "r"(a), "r"(bytes) : "memory");
}
__device__ __forceinline__ void bulk_g2s(uint32_t dst, const void* src,
                                         uint32_t bytes, uint32_t mbar) {
    asm volatile("cp.async.bulk.shared::cta.global.mbarrier::complete_tx::bytes "
                 "[%0], [%1], %2, [%3];"
                 :: "r"(dst), "l"(src), "r"(bytes), "r"(mbar) : "memory");
}

__device__ __forceinline__ void ldsm4(unsigned& r0, unsigned& r1,
                                      unsigned& r2, unsigned& r3, uint32_t addr) {
    asm volatile("ldmatrix.sync.aligned.m8n8.x4.shared.b16 {%0,%1,%2,%3}, [%4];"
                 : "=r"(r0), "=r"(r1), "=r"(r2), "=r"(r3) : "r"(addr));
}
__device__ __forceinline__ void mmabf(float d[4], const unsigned a[4],
                                      unsigned b0, unsigned b1) {
    asm volatile("mma.sync.aligned.m16n8k16.row.col.f32.bf16.bf16.f32 "
                 "{%0,%1,%2,%3}, {%4,%5,%6,%7}, {%8,%9}, {%0,%1,%2,%3};"
                 : "+f"(d[0]), "+f"(d[1]), "+f"(d[2]), "+f"(d[3])
                 : "r"(a[0]), "r"(a[1]), "r"(a[2]), "r"(a[3]), "r"(b0), "r"(b1));
}
__device__ __forceinline__ void mma8(float d[4], const unsigned a[4],
                                     unsigned b0, unsigned b1) {
    asm volatile("mma.sync.aligned.m16n8k8.row.col.f32.tf32.tf32.f32 "
                 "{%0,%1,%2,%3}, {%4,%5,%6,%7}, {%8,%9}, {%0,%1,%2,%3};"
                 : "+f"(d[0]), "+f"(d[1]), "+f"(d[2]), "+f"(d[3])
                 : "r"(a[0]), "r"(a[1]), "r"(a[2]), "r"(a[3]), "r"(b0), "r"(b1));
}

__device__ __forceinline__ float sigf(float x) {
    return __fdividef(1.f, 1.f + __expf(-x));
}
__device__ __forceinline__ float tanhfast(float x) {
    return 1.f - __fdividef(2.f, __expf(2.f * x) + 1.f);
}

// ---------------------------------------------------------------------------
// Precompute
// ---------------------------------------------------------------------------
__global__ void prep_w(const float* __restrict__ Whh, const float* __restrict__ Wout) {
    const int nB = 16 * 16 * 96 * 32;
    const int ntot = nB + HID * VOC;
    for (int idx = blockIdx.x * blockDim.x + threadIdx.x; idx < ntot;
         idx += gridDim.x * blockDim.x) {
        if (idx < nB) {
            int kk  = idx & 31;
            int c   = (idx >> 5) % 96;
            int rest= (idx >> 5) / 96;
            int ktl = rest & 15, jt = rest >> 4;
            int blk = c / 48, r48 = c % 48;
            int g = r48 >> 4, jjw = r48 & 15;
            int n = g * HID + jt * 32 + blk * 16 + jjw;
            int k = ktl * 32 + kk;
            g_Wst[((size_t)(jt * 16 + ktl) * 96 + c) * 40 + kk] =
                __float2bfloat16_rn(Whh[(size_t)n * HID + k]);
        } else {
            int j = idx - nB, v = j / HID, k = j % HID;
            g_WoT[k * VOC + v] = tf32r(Wout[j]);
        }
    }
}

// GI2[v][n]: n<1024 -> gi+bhh (r,z); 1024..1535 -> gi_n; 1536..2047 -> bhh_n
__global__ void prep_gi(const float* __restrict__ emb, const float* __restrict__ Wih,
                        const float* __restrict__ bih, const float* __restrict__ bhh) {
    __shared__ float x[EMBD];
    const int v = blockIdx.x;
    if (threadIdx.x < EMBD) x[threadIdx.x] = fmaxf(emb[v * EMBD + threadIdx.x], 0.f);
    __syncthreads();
    for (int n = threadIdx.x; n < 2048; n += blockDim.x) {
        if (n < G3) {
            float acc = bih[n];
            const float* w = Wih + n * EMBD;
#pragma unroll
            for (int e = 0; e < EMBD; e++) acc += x[e] * w[e];
            if (n < 1024) acc += bhh[n];
            g_GI2[v * 2048 + n] = acc;
        } else {
            g_GI2[v * 2048 + n] = bhh[1024 + (n - G3)];
        }
    }
}

__global__ void init_h(const float* __restrict__ eh) {
    if (blockIdx.x == 0)
        for (int q = threadIdx.x; q < 16 * 32; q += blockDim.x) g_mbar[q] = 0;
    for (int i = blockIdx.x * blockDim.x + threadIdx.x; i < BSZ * HID;
         i += gridDim.x * blockDim.x) {
        float h = eh[i];
        int b = i >> 9, k = i & 511;
        g_Hall[i] = h;
        g_Hab[((size_t)(b >> 7) * 16 + (k >> 5)) * ABLK
              + (size_t)(b & 127) * 40 + (k & 31)] = __float2bfloat16_rn(h);
    }
}

// ---------------------------------------------------------------------------
// Persistent GRU. Grid (16 j, 16 m) = 256 CTAs, 128 threads = 4 warps
// (2M x 2N, warp tile 64x48), 2 CTAs/SM. Per-m 16-CTA barriers per step.
// ---------------------------------------------------------------------------
__global__ void __launch_bounds__(128, 2)
gru_persist(const int* __restrict__ tgt) {
    extern __shared__ __align__(128) unsigned char smraw[];
    __shared__ __align__(8) unsigned long long s_mbA[4], s_mbB[4];

    const int tid  = threadIdx.x;
    const int lane = tid & 31, w = tid >> 5;
    const int l3 = lane & 3, q2 = lane >> 2;
    const int wm = (w >> 1) * 64;      // warp M offset (0 or 64)
    const int wn = (w & 1);            // warp N group (16 jj)
    const int m0 = blockIdx.y * 128;
    const int j0 = blockIdx.x * 32;

    const uint32_t sbA = smem_u32(smraw);
    const uint32_t sbB = sbA + A_RING;
    uint32_t mbA[4], mbB[4];
#pragma unroll
    for (int s = 0; s < 4; s++) { mbA[s] = smem_u32(&s_mbA[s]); mbB[s] = smem_u32(&s_mbB[s]); }

    if (tid == 0) {
#pragma unroll
        for (int s = 0; s < 4; s++) { mb_init(mbA[s], 1); mb_init(mbB[s], 1); }
    }
    __syncthreads();

    const __nv_bfloat16* __restrict__ Bsrc = g_Wst + (size_t)blockIdx.x * 16 * BBLK;
    unsigned* const barp = &g_mbar[blockIdx.y * 32];

    auto issueA = [&](int c) {       // c = 16t + kt
        const int s = c & 3;
        mb_expect(mbA[s], 10240u);
        const __nv_bfloat16* src = g_Hab +
            ((size_t)(c >> 4) * 256 + (size_t)blockIdx.y * 16 + (c & 15)) * ABLK;
        bulk_g2s(sbA + (uint32_t)s * 10240u, src, 10240u, mbA[s]);
    };
    auto issueB = [&](int c) {
        const int s = c & 3;
        mb_expect(mbB[s], 7680u);
        bulk_g2s(sbB + (uint32_t)s * 7680u, Bsrc + (size_t)(c & 15) * BBLK, 7680u, mbB[s]);
    };

    if (tid == 0) { issueB(0); issueB(1); issueB(2); issueA(0); issueA(1); issueA(2); }

    // ldmatrix lane offsets (within one ring slot)
    const uint32_t offA = (uint32_t)(wm + (lane & 15)) * 80u + (uint32_t)(lane >> 4) * 16u;
    const uint32_t offB = (uint32_t)(wn * 48 + (lane & 7)) * 80u + (uint32_t)(lane >> 3) * 16u;

    for (int t = 0; t < TLEN; t++) {
        const int base = t << 4;

        float d[4][6][4];
#pragma unroll
        for (int a = 0; a < 4; a++)
#pragma unroll
            for (int b = 0; b < 6; b++)
#pragma unroll
                for (int c = 0; c < 4; c++) d[a][b][c] = 0.f;

        for (int kt = 0; kt < 16; kt++) {
            const int c = base + kt;
            if (tid == 0) {
                if (c + 3 < TLEN * 16) issueB(c + 3);
                if (kt < 13) issueA(c + 3);
            }
            const uint32_t par = (uint32_t)((c >> 2) & 1);
            mb_wait(mbA[c & 3], par);
            mb_wait(mbB[c & 3], par);

            const uint32_t stA = sbA + (uint32_t)(c & 3) * 10240u;
            const uint32_t stB = sbB + (uint32_t)(c & 3) * 7680u;

            unsigned b[6][4];
#pragma unroll
            for (int nf = 0; nf < 6; nf++)
                ldsm4(b[nf][0], b[nf][1], b[nf][2], b[nf][3],
                      stB + offB + (uint32_t)nf * (8u * 80u));

#pragma unroll
            for (int ks = 0; ks < 2; ks++) {
                unsigned a[4][4];
#pragma unroll
                for (int mf = 0; mf < 4; mf++)
                    ldsm4(a[mf][0], a[mf][1], a[mf][2], a[mf][3],
                          stA + offA + (uint32_t)mf * (16u * 80u) + (uint32_t)ks * 32u);
#pragma unroll
                for (int nf = 0; nf < 6; nf++)
#pragma unroll
                    for (int mf = 0; mf < 4; mf++)
                        mmabf(d[mf][nf], a[mf], b[nf][ks * 2], b[nf][ks * 2 + 1]);
            }

            if (kt < 15) __syncthreads();         // release ring slot
        }

        // ---- register GRU epilogue ----
        const float* __restrict__ Hc = g_Hall + (size_t)t * BSZ * HID;
        float* __restrict__ Ha = g_Hall + (size_t)(t + 1) * BSZ * HID;
        __nv_bfloat16* __restrict__ Hb =
            g_Hab + ((size_t)(t + 1) * 256 + (size_t)blockIdx.y * 16 + blockIdx.x) * ABLK;
#pragma unroll
        for (int mf = 0; mf < 4; mf++) {
#pragma unroll
            for (int rh = 0; rh < 2; rh++) {
                const int lrow = wm + mf * 16 + q2 + rh * 8;
                const int row  = m0 + lrow;
                const int tok = (t == 0) ? 0 : __ldg(tgt + row * TLEN + t - 1);
                const float* __restrict__ T = g_GI2 + tok * 2048;
#pragma unroll
                for (int jf = 0; jf < 2; jf++) {
                    const int lcol = wn * 16 + jf * 8 + l3 * 2;
                    const int j2 = j0 + lcol;
                    float h[2];
#pragma unroll
                    for (int p = 0; p < 2; p++) {
                        const int r = rh * 2 + p;
                        const int j = j2 + p;
                        float gr  = d[mf][jf][r]     + T[j];            // gi_r+bhh_r
                        float gz  = d[mf][2 + jf][r] + T[512 + j];      // gi_z+bhh_z
                        float ghn = d[mf][4 + jf][r] + T[1536 + j];     // bhh_n
                        float rr = sigf(gr);
                        float zz = sigf(gz);
                        float nn = tanhfast(T[1024 + j] + rr * ghn);    // gi_n
                        float ho = Hc[(size_t)row * HID + j];
                        h[p] = fmaf(zz, ho - nn, nn);
                    }
                    *reinterpret_cast<float2*>(Ha + (size_t)row * HID + j2) =
                        make_float2(h[0], h[1]);
                    *reinterpret_cast<__nv_bfloat162*>(Hb + (size_t)lrow * 40 + lcol) =
                        __floats2bfloat162_rn(h[0], h[1]);
                }
            }
        }

        // ---- per-m-block barrier (16 CTAs) + next-step A issues ----
        if (t < TLEN - 1) {
            __syncthreads();
            if (tid == 0) {
                asm volatile("red.release.gpu.add.u32 [%0], %1;"
                             :: "l"(barp), "r"(1u) : "memory");
                const unsigned target = 16u * (unsigned)(t + 1);
                unsigned v;
                do {
                    asm volatile("ld.acquire.gpu.u32 %0, [%1];"
                                 : "=r"(v) : "l"(barp) : "memory");
                    if (v < target) __nanosleep(64);
                } while (v < target);
                asm volatile("fence.proxy.async;" ::: "memory");
                issueA(base + 16); issueA(base + 17); issueA(base + 18);
            }
            __syncthreads();
        }
    }
}

// ---------------------------------------------------------------------------
// Batched logits (tf32): (160*2048) x 128 x 512 GEMM + log_softmax.
// A = fp32 hidden history; mma.tf32 truncates low mantissa bits in-HW.
// ---------------------------------------------------------------------------
__global__ void __launch_bounds__(256, 1)
logits_all(const float* __restrict__ bout, float* __restrict__ out) {
    extern __shared__ float sm[];
    float* ep = sm;

    const int tid = threadIdx.x, lane = tid & 31, w = tid >> 5;
    const int l3 = lane & 3, q2 = lane >> 2;
    const int wm = (w >> 1) * 32, wn = (w & 1) * 64;
    const int m0 = blockIdx.x * 128;

    const float* __restrict__ A = g_Hall + (size_t)BSZ * HID;   // slots 1..160

    float d[2][8][4];
#pragma unroll
    for (int a = 0; a < 2; a++)
#pragma unroll
        for (int b = 0; b < 8; b++)
#pragma unroll
            for (int c = 0; c < 4; c++) d[a][b][c] = 0.f;

    auto load_tile = [&](int buf, int k0) {
        float* As = sm + buf * SBUF2;
        float* Bs = As + 128 * AS_LD;
#pragma unroll
        for (int i = 0; i < 4; i++) {
            int f = i * 256 + tid, row = f >> 3, q = f & 7;
            cpa16(As + row * AS_LD + q * 4, A + (size_t)(m0 + row) * HID + k0 + q * 4);
        }
#pragma unroll
        for (int i = 0; i < 4; i++) {
            int f = i * 256 + tid, k = f >> 5, q = f & 31;
            cpa16(Bs + k * BS2_LD + q * 4, g_WoT + (k0 + k) * VOC + q * 4);
        }
    };

    load_tile(0, 0);
    CP_COMMIT();
    CP_WAIT(0);
    __syncthreads();

    for (int kt = 0; kt < 16; kt++) {
        if (kt < 15) { load_tile((kt + 1) & 1, (kt + 1) * 32); CP_COMMIT(); }
        const float* As = sm + (kt & 1) * SBUF2;
        const float* Bs = As + 128 * AS_LD;
#pragma unroll
        for (int ks = 0; ks < 4; ks++) {
            const int kk = ks * 8;
            unsigned a[2][4];
#pragma unroll
            for (int mf = 0; mf < 2; mf++) {
                int r = wm + mf * 16 + q2;
                a[mf][0] = __float_as_uint(As[r * AS_LD + kk + l3]);
                a[mf][1] = __float_as_uint(As[(r + 8) * AS_LD + kk + l3]);
                a[mf][2] = __float_as_uint(As[r * AS_LD + kk + 4 + l3]);
                a[mf][3] = __float_as_uint(As[(r + 8) * AS_LD + kk + 4 + l3]);
            }
#pragma unroll
            for (int nf = 0; nf < 8; nf++) {
                int col = wn + nf * 8 + q2;
                unsigned b0 = __float_as_uint(Bs[(kk + l3) * BS2_LD + col]);
                unsigned b1 = __float_as_uint(Bs[(kk + 4 + l3) * BS2_LD + col]);
                mma8(d[0][nf], a[0], b0, b1);
                mma8(d[1][nf], a[1], b0, b1);
            }
        }
        if (kt < 15) { CP_WAIT(0); __syncthreads(); }
    }

    __syncthreads();

#pragma unroll
    for (int mf = 0; mf < 2; mf++)
#pragma unroll
        for (int nf = 0; nf < 8; nf++)
#pragma unroll
            for (int rh = 0; rh < 2; rh++) {
                int r = wm + mf * 16 + q2 + rh * 8;
                int col = wn + nf * 8 + l3 * 2;
                *reinterpret_cast<float2*>(ep + r * EP_LD + col) =
                    make_float2(d[mf][nf][rh * 2], d[mf][nf][rh * 2 + 1]);
            }
    __syncthreads();

    for (int i = 0; i < 16; i++) {
        int row = w * 16 + i;
        float x[4];
        float mx = -1e30f;
#pragma unroll
        for (int q = 0; q < 4; q++) {
            int v = lane + q * 32;
            x[q] = ep[row * EP_LD + v] + bout[v];
            mx = fmaxf(mx, x[q]);
        }
#pragma unroll
        for (int off = 16; off > 0; off >>= 1)
            mx = fmaxf(mx, __shfl_xor_sync(0xffffffffu, mx, off));
        float s = 0.f;
#pragma unroll
        for (int q = 0; q < 4; q++) s += expf(x[q] - mx);
#pragma unroll
        for (int off = 16; off > 0; off >>= 1)
            s += __shfl_xor_sync(0xffffffffu, s, off);
        float L = mx + logf(s);
        float* orow = out + (size_t)(m0 + row) * VOC;
#pragma unroll
        for (int q = 0; q < 4; q++) orow[lane + q * 32] = x[q] - L;
    }
}

__global__ void finalize_h(float* __restrict__ out) {
    float* dst = out + (size_t)TLEN * BSZ * VOC;
    const float* src = g_Hall + (size_t)TLEN * BSZ * HID;
    for (int i = blockIdx.x * blockDim.x + threadIdx.x; i < BSZ * HID;
         i += gridDim.x * blockDim.x)
        dst[i] = src[i];
}

// ---------------------------------------------------------------------------
extern "C" void kernel_launch(void* const* d_in, const int* in_sizes, int n_in,
                              void* d_out, int out_size) {
    (void)in_sizes; (void)n_in; (void)out_size;
    const float* enc_h = (const float*)d_in[1];
    const int*   tgt   = (const int*)d_in[2];
    const float* emb   = (const float*)d_in[3];
    const float* Wih   = (const float*)d_in[4];
    const float* Whh   = (const float*)d_in[5];
    const float* bih   = (const float*)d_in[6];
    const float* bhh   = (const float*)d_in[7];
    const float* Wout  = (const float*)d_in[8];
    const float* bout  = (const float*)d_in[9];
    float* out = (float*)d_out;

    const int log_smem = 2 * SBUF2 * 4;          // 71680 B
    cudaFuncSetAttribute(gru_persist, cudaFuncAttributeMaxDynamicSharedMemorySize, GRU_SMEM);
    cudaFuncSetAttribute(logits_all,  cudaFuncAttributeMaxDynamicSharedMemorySize, log_smem);

    prep_w <<<512, 256>>>(Whh, Wout);
    prep_gi<<<VOC, 256>>>(emb, Wih, bih, bhh);
    init_h <<<1024, 256>>>(enc_h);

    gru_persist<<<dim3(16, 16), 128, GRU_SMEM>>>(tgt);

    logits_all<<<(TLEN * BSZ) / 128, 256, log_smem>>>(bout, out);
    finalize_h<<<1024, 256>>>(out);
}

// round 17
// speedup vs baseline: 1.0339x; 1.0339x over previous
#include <cuda_runtime.h>
#include <cuda_bf16.h>
#include <cstdint>
#include <cmath>

// ---------------------------------------------------------------------------
// DecoderRNN, persistent-GRU (R15 mainloop + R16 traffic cuts):
//  * 256 thr / 8 warps (4M x 2N, warp tile 32x48) — proven occupancy (2/SM)
//  * h stored once, fp32, in g_Hall (logits tf32 mma truncates in-HW)
//  * token table GI2[v][2048] = gi_r+bhh_r | gi_z+bhh_z | gi_n | bhh_n
//  * per-m-block 16-CTA barriers; split A/B cp.async.bulk rings (B crosses
//    the barrier); ldmatrix.x4 fragments; mma m16n8k16 bf16; fp32 gates
//  * ONE batched tf32 logits GEMM + fused log_softmax at the end
// Output: [160*2048*128 log_probs fp32][2048*512 final hidden fp32]
// ---------------------------------------------------------------------------

#define HID   512
#define VOC   128
#define EMBD  64
#define BSZ   2048
#define TLEN  160
#define G3    1536

#define ABLK   (128 * 40)            // 10240 B per A tile
#define BBLK   (96 * 40)             //  7680 B per B tile
#define A_RING (4 * 10240)
#define B_RING (4 * 7680)
#define GRU_SMEM (A_RING + B_RING)   // 71680 B (2 CTAs/SM)

// logits tf32 tiling (proven path, unchanged)
#define AS_LD  36
#define BS2_LD 136
#define EP_LD  132
#define SBUF2  (128 * AS_LD + 32 * BS2_LD)

// Static scratch
__device__ __nv_bfloat16 g_Wst[16 * 16 * BBLK];          // W_hh bf16, tiled
__device__ float g_WoT [HID * VOC];                      // W_out^T tf32 [k][v]
__device__ float g_GI2 [VOC * 2048];                     // fused token table
__device__ float g_Hall[(size_t)(TLEN + 1) * BSZ * HID]; // fp32 hidden history
__device__ __nv_bfloat16 g_Hab[(size_t)(TLEN + 1) * 256 * ABLK]; // bf16 tiled hidden
__device__ unsigned g_mbar[16 * 32];                     // per-m barriers, 128B apart

__device__ __forceinline__ float tf32r(float x) {
    unsigned u;
    asm("cvt.rna.tf32.f32 %0, %1;" : "=r"(u) : "f"(x));
    return __uint_as_float(u);
}
__device__ __forceinline__ uint32_t smem_u32(const void* p) {
    uint32_t a;
    asm("{ .reg .u64 t; cvta.to.shared.u64 t, %1; cvt.u32.u64 %0, t; }" : "=r"(a) : "l"(p));
    return a;
}
__device__ __forceinline__ void cpa16(const void* dst, const void* src) {
    unsigned d = (unsigned)__cvta_generic_to_shared(dst);
    asm volatile("cp.async.cg.shared.global [%0], [%1], 16;" :: "r"(d), "l"(src));
}
#define CP_COMMIT() asm volatile("cp.async.commit_group;")
#define CP_WAIT(n)  asm volatile("cp.async.wait_group %0;" :: "n"(n))

__device__ __forceinline__ void mb_init(uint32_t a, uint32_t cnt) {
    asm volatile("mbarrier.init.shared.b64 [%0], %1;" :: "r"(a), "r"(cnt) : "memory");
}
__device__ __forceinline__ void mb_wait(uint32_t a, uint32_t parity) {
    asm volatile(
        "{\n\t.reg .pred P;\n\t"
        "W_%=:\n\t"
        "mbarrier.try_wait.parity.acquire.cta.shared::cta.b64 P, [%0], %1, 0x989680;\n\t"
        "@P bra.uni D_%=;\n\t"
        "bra.uni W_%=;\n\t"
        "D_%=:\n\t}"
        :: "r"(a), "r"(parity) : "memory");
}
__device__ __forceinline__ void mb_expect(uint32_t a, uint32_t bytes) {
    asm volatile("mbarrier.arrive.expect_tx.shared.b64 _, [%0], %1;"
                 :: "r"(a), "r"(bytes) : "memory");
}
__device__ __forceinline__ void bulk_g2s(uint32_t dst, const void* src,
                                         uint32_t bytes, uint32_t mbar) {
    asm volatile("cp.async.bulk.shared::cta.global.mbarrier::complete_tx::bytes "
                 "[%0], [%1], %2, [%3];"
                 :: "r"(dst), "l"(src), "r"(bytes), "r"(mbar) : "memory");
}

__device__ __forceinline__ void ldsm4(unsigned& r0, unsigned& r1,
                                      unsigned& r2, unsigned& r3, uint32_t addr) {
    asm volatile("ldmatrix.sync.aligned.m8n8.x4.shared.b16 {%0,%1,%2,%3}, [%4];"
                 : "=r"(r0), "=r"(r1), "=r"(r2), "=r"(r3) : "r"(addr));
}
__device__ __forceinline__ void mmabf(float d[4], const unsigned a[4],
                                      unsigned b0, unsigned b1) {
    asm volatile("mma.sync.aligned.m16n8k16.row.col.f32.bf16.bf16.f32 "
                 "{%0,%1,%2,%3}, {%4,%5,%6,%7}, {%8,%9}, {%0,%1,%2,%3};"
                 : "+f"(d[0]), "+f"(d[1]), "+f"(d[2]), "+f"(d[3])
                 : "r"(a[0]), "r"(a[1]), "r"(a[2]), "r"(a[3]), "r"(b0), "r"(b1));
}
__device__ __forceinline__ void mma8(float d[4], const unsigned a[4],
                                     unsigned b0, unsigned b1) {
    asm volatile("mma.sync.aligned.m16n8k8.row.col.f32.tf32.tf32.f32 "
                 "{%0,%1,%2,%3}, {%4,%5,%6,%7}, {%8,%9}, {%0,%1,%2,%3};"
                 : "+f"(d[0]), "+f"(d[1]), "+f"(d[2]), "+f"(d[3])
                 : "r"(a[0]), "r"(a[1]), "r"(a[2]), "r"(a[3]), "r"(b0), "r"(b1));
}

__device__ __forceinline__ float sigf(float x) {
    return __fdividef(1.f, 1.f + __expf(-x));
}
__device__ __forceinline__ float tanhfast(float x) {
    return 1.f - __fdividef(2.f, __expf(2.f * x) + 1.f);
}

// ---------------------------------------------------------------------------
// Precompute
// ---------------------------------------------------------------------------
__global__ void prep_w(const float* __restrict__ Whh, const float* __restrict__ Wout) {
    const int nB = 16 * 16 * 96 * 32;
    const int ntot = nB + HID * VOC;
    for (int idx = blockIdx.x * blockDim.x + threadIdx.x; idx < ntot;
         idx += gridDim.x * blockDim.x) {
        if (idx < nB) {
            int kk  = idx & 31;
            int c   = (idx >> 5) % 96;
            int rest= (idx >> 5) / 96;
            int ktl = rest & 15, jt = rest >> 4;
            int blk = c / 48, r48 = c % 48;
            int g = r48 >> 4, jjw = r48 & 15;
            int n = g * HID + jt * 32 + blk * 16 + jjw;
            int k = ktl * 32 + kk;
            g_Wst[((size_t)(jt * 16 + ktl) * 96 + c) * 40 + kk] =
                __float2bfloat16_rn(Whh[(size_t)n * HID + k]);
        } else {
            int j = idx - nB, v = j / HID, k = j % HID;
            g_WoT[k * VOC + v] = tf32r(Wout[j]);
        }
    }
}

// GI2[v][n]: n<1024 -> gi+bhh (r,z); 1024..1535 -> gi_n; 1536..2047 -> bhh_n
__global__ void prep_gi(const float* __restrict__ emb, const float* __restrict__ Wih,
                        const float* __restrict__ bih, const float* __restrict__ bhh) {
    __shared__ float x[EMBD];
    const int v = blockIdx.x;
    if (threadIdx.x < EMBD) x[threadIdx.x] = fmaxf(emb[v * EMBD + threadIdx.x], 0.f);
    __syncthreads();
    for (int n = threadIdx.x; n < 2048; n += blockDim.x) {
        if (n < G3) {
            float acc = bih[n];
            const float* w = Wih + n * EMBD;
#pragma unroll
            for (int e = 0; e < EMBD; e++) acc += x[e] * w[e];
            if (n < 1024) acc += bhh[n];
            g_GI2[v * 2048 + n] = acc;
        } else {
            g_GI2[v * 2048 + n] = bhh[1024 + (n - G3)];
        }
    }
}

__global__ void init_h(const float* __restrict__ eh) {
    if (blockIdx.x == 0)
        for (int q = threadIdx.x; q < 16 * 32; q += blockDim.x) g_mbar[q] = 0;
    for (int i = blockIdx.x * blockDim.x + threadIdx.x; i < BSZ * HID;
         i += gridDim.x * blockDim.x) {
        float h = eh[i];
        int b = i >> 9, k = i & 511;
        g_Hall[i] = h;
        g_Hab[((size_t)(b >> 7) * 16 + (k >> 5)) * ABLK
              + (size_t)(b & 127) * 40 + (k & 31)] = __float2bfloat16_rn(h);
    }
}

// ---------------------------------------------------------------------------
// Persistent GRU. Grid (16 j, 16 m) = 256 CTAs, 256 threads = 8 warps
// (4M x 2N, warp tile 32x48), 2 CTAs/SM. Per-m 16-CTA barriers per step.
// ---------------------------------------------------------------------------
__global__ void __launch_bounds__(256, 2)
gru_persist(const int* __restrict__ tgt) {
    extern __shared__ __align__(128) unsigned char smraw[];
    __shared__ __align__(8) unsigned long long s_mbA[4], s_mbB[4];

    const int tid  = threadIdx.x;
    const int lane = tid & 31, w = tid >> 5;
    const int l3 = lane & 3, q2 = lane >> 2;
    const int wm = (w >> 1) * 32;      // warp M offset (0,32,64,96)
    const int wn = (w & 1);            // warp N group (16 jj)
    const int m0 = blockIdx.y * 128;
    const int j0 = blockIdx.x * 32;

    const uint32_t sbA = smem_u32(smraw);
    const uint32_t sbB = sbA + A_RING;
    uint32_t mbA[4], mbB[4];
#pragma unroll
    for (int s = 0; s < 4; s++) { mbA[s] = smem_u32(&s_mbA[s]); mbB[s] = smem_u32(&s_mbB[s]); }

    if (tid == 0) {
#pragma unroll
        for (int s = 0; s < 4; s++) { mb_init(mbA[s], 1); mb_init(mbB[s], 1); }
    }
    __syncthreads();

    const __nv_bfloat16* __restrict__ Bsrc = g_Wst + (size_t)blockIdx.x * 16 * BBLK;
    unsigned* const barp = &g_mbar[blockIdx.y * 32];

    auto issueA = [&](int c) {       // c = 16t + kt
        const int s = c & 3;
        mb_expect(mbA[s], 10240u);
        const __nv_bfloat16* src = g_Hab +
            ((size_t)(c >> 4) * 256 + (size_t)blockIdx.y * 16 + (c & 15)) * ABLK;
        bulk_g2s(sbA + (uint32_t)s * 10240u, src, 10240u, mbA[s]);
    };
    auto issueB = [&](int c) {
        const int s = c & 3;
        mb_expect(mbB[s], 7680u);
        bulk_g2s(sbB + (uint32_t)s * 7680u, Bsrc + (size_t)(c & 15) * BBLK, 7680u, mbB[s]);
    };

    if (tid == 0) { issueB(0); issueB(1); issueB(2); issueA(0); issueA(1); issueA(2); }

    // ldmatrix lane offsets (within one ring slot)
    const uint32_t offA = (uint32_t)(wm + (lane & 15)) * 80u + (uint32_t)(lane >> 4) * 16u;
    const uint32_t offB = (uint32_t)(wn * 48 + (lane & 7)) * 80u + (uint32_t)(lane >> 3) * 16u;

    for (int t = 0; t < TLEN; t++) {
        const int base = t << 4;

        float d[2][6][4];
#pragma unroll
        for (int a = 0; a < 2; a++)
#pragma unroll
            for (int b = 0; b < 6; b++)
#pragma unroll
                for (int c = 0; c < 4; c++) d[a][b][c] = 0.f;

        for (int kt = 0; kt < 16; kt++) {
            const int c = base + kt;
            if (tid == 0) {
                if (c + 3 < TLEN * 16) issueB(c + 3);
                if (kt < 13) issueA(c + 3);       // same-step A only
            }
            const uint32_t par = (uint32_t)((c >> 2) & 1);
            mb_wait(mbA[c & 3], par);
            mb_wait(mbB[c & 3], par);

            const uint32_t stA = sbA + (uint32_t)(c & 3) * 10240u;
            const uint32_t stB = sbB + (uint32_t)(c & 3) * 7680u;

            unsigned a[2][2][4];                  // [ks][mf][4]
#pragma unroll
            for (int mf = 0; mf < 2; mf++)
#pragma unroll
                for (int ks = 0; ks < 2; ks++)
                    ldsm4(a[ks][mf][0], a[ks][mf][1], a[ks][mf][2], a[ks][mf][3],
                          stA + offA + (uint32_t)mf * (16u * 80u) + (uint32_t)ks * 32u);

            unsigned b[6][4];
#pragma unroll
            for (int nf = 0; nf < 6; nf++)
                ldsm4(b[nf][0], b[nf][1], b[nf][2], b[nf][3],
                      stB + offB + (uint32_t)nf * (8u * 80u));

#pragma unroll
            for (int ks = 0; ks < 2; ks++)
#pragma unroll
                for (int nf = 0; nf < 6; nf++) {
                    mmabf(d[0][nf], a[ks][0], b[nf][ks * 2], b[nf][ks * 2 + 1]);
                    mmabf(d[1][nf], a[ks][1], b[nf][ks * 2], b[nf][ks * 2 + 1]);
                }

            if (kt < 15) __syncthreads();         // release ring slot
        }

        // ---- register GRU epilogue (GI2 table, single fp32 Hall) ----
        const float* __restrict__ Hc = g_Hall + (size_t)t * BSZ * HID;
        float* __restrict__ Ha = g_Hall + (size_t)(t + 1) * BSZ * HID;
        __nv_bfloat16* __restrict__ Hb =
            g_Hab + ((size_t)(t + 1) * 256 + (size_t)blockIdx.y * 16 + blockIdx.x) * ABLK;
#pragma unroll
        for (int mf = 0; mf < 2; mf++) {
#pragma unroll
            for (int rh = 0; rh < 2; rh++) {
                const int lrow = wm + mf * 16 + q2 + rh * 8;
                const int row  = m0 + lrow;
                const int tok = (t == 0) ? 0 : __ldg(tgt + row * TLEN + t - 1);
                const float* __restrict__ T = g_GI2 + tok * 2048;
#pragma unroll
                for (int jf = 0; jf < 2; jf++) {
                    const int lcol = wn * 16 + jf * 8 + l3 * 2;
                    const int j2 = j0 + lcol;
                    float h[2];
#pragma unroll
                    for (int p = 0; p < 2; p++) {
                        const int r = rh * 2 + p;
                        const int j = j2 + p;
                        float gr  = d[mf][jf][r]     + T[j];            // gi_r+bhh_r
                        float gz  = d[mf][2 + jf][r] + T[512 + j];      // gi_z+bhh_z
                        float ghn = d[mf][4 + jf][r] + T[1536 + j];     // bhh_n
                        float rr = sigf(gr);
                        float zz = sigf(gz);
                        float nn = tanhfast(T[1024 + j] + rr * ghn);    // gi_n
                        float ho = Hc[(size_t)row * HID + j];
                        h[p] = fmaf(zz, ho - nn, nn);
                    }
                    *reinterpret_cast<float2*>(Ha + (size_t)row * HID + j2) =
                        make_float2(h[0], h[1]);
                    *reinterpret_cast<__nv_bfloat162*>(Hb + (size_t)lrow * 40 + lcol) =
                        __floats2bfloat162_rn(h[0], h[1]);
                }
            }
        }

        // ---- per-m-block barrier (16 CTAs) + next-step A issues ----
        if (t < TLEN - 1) {
            __syncthreads();
            if (tid == 0) {
                asm volatile("red.release.gpu.add.u32 [%0], %1;"
                             :: "l"(barp), "r"(1u) : "memory");
                const unsigned target = 16u * (unsigned)(t + 1);
                unsigned v;
                do {
                    asm volatile("ld.acquire.gpu.u32 %0, [%1];"
                                 : "=r"(v) : "l"(barp) : "memory");
                    if (v < target) __nanosleep(64);
                } while (v < target);
                asm volatile("fence.proxy.async;" ::: "memory");
                issueA(base + 16); issueA(base + 17); issueA(base + 18);
            }
            __syncthreads();
        }
    }
}

// ---------------------------------------------------------------------------
// Batched logits (tf32): (160*2048) x 128 x 512 GEMM + log_softmax.
// A = fp32 hidden history; mma.tf32 truncates low mantissa bits in-HW.
// ---------------------------------------------------------------------------
__global__ void __launch_bounds__(256, 1)
logits_all(const float* __restrict__ bout, float* __restrict__ out) {
    extern __shared__ float sm[];
    float* ep = sm;

    const int tid = threadIdx.x, lane = tid & 31, w = tid >> 5;
    const int l3 = lane & 3, q2 = lane >> 2;
    const int wm = (w >> 1) * 32, wn = (w & 1) * 64;
    const int m0 = blockIdx.x * 128;

    const float* __restrict__ A = g_Hall + (size_t)BSZ * HID;   // slots 1..160

    float d[2][8][4];
#pragma unroll
    for (int a = 0; a < 2; a++)
#pragma unroll
        for (int b = 0; b < 8; b++)
#pragma unroll
            for (int c = 0; c < 4; c++) d[a][b][c] = 0.f;

    auto load_tile = [&](int buf, int k0) {
        float* As = sm + buf * SBUF2;
        float* Bs = As + 128 * AS_LD;
#pragma unroll
        for (int i = 0; i < 4; i++) {
            int f = i * 256 + tid, row = f >> 3, q = f & 7;
            cpa16(As + row * AS_LD + q * 4, A + (size_t)(m0 + row) * HID + k0 + q * 4);
        }
#pragma unroll
        for (int i = 0; i < 4; i++) {
            int f = i * 256 + tid, k = f >> 5, q = f & 31;
            cpa16(Bs + k * BS2_LD + q * 4, g_WoT + (k0 + k) * VOC + q * 4);
        }
    };

    load_tile(0, 0);
    CP_COMMIT();
    CP_WAIT(0);
    __syncthreads();

    for (int kt = 0; kt < 16; kt++) {
        if (kt < 15) { load_tile((kt + 1) & 1, (kt + 1) * 32); CP_COMMIT(); }
        const float* As = sm + (kt & 1) * SBUF2;
        const float* Bs = As + 128 * AS_LD;
#pragma unroll
        for (int ks = 0; ks < 4; ks++) {
            const int kk = ks * 8;
            unsigned a[2][4];
#pragma unroll
            for (int mf = 0; mf < 2; mf++) {
                int r = wm + mf * 16 + q2;
                a[mf][0] = __float_as_uint(As[r * AS_LD + kk + l3]);
                a[mf][1] = __float_as_uint(As[(r + 8) * AS_LD + kk + l3]);
                a[mf][2] = __float_as_uint(As[r * AS_LD + kk + 4 + l3]);
                a[mf][3] = __float_as_uint(As[(r + 8) * AS_LD + kk + 4 + l3]);
            }
#pragma unroll
            for (int nf = 0; nf < 8; nf++) {
                int col = wn + nf * 8 + q2;
                unsigned b0 = __float_as_uint(Bs[(kk + l3) * BS2_LD + col]);
                unsigned b1 = __float_as_uint(Bs[(kk + 4 + l3) * BS2_LD + col]);
                mma8(d[0][nf], a[0], b0, b1);
                mma8(d[1][nf], a[1], b0, b1);
            }
        }
        if (kt < 15) { CP_WAIT(0); __syncthreads(); }
    }

    __syncthreads();

#pragma unroll
    for (int mf = 0; mf < 2; mf++)
#pragma unroll
        for (int nf = 0; nf < 8; nf++)
#pragma unroll
            for (int rh = 0; rh < 2; rh++) {
                int r = wm + mf * 16 + q2 + rh * 8;
                int col = wn + nf * 8 + l3 * 2;
                *reinterpret_cast<float2*>(ep + r * EP_LD + col) =
                    make_float2(d[mf][nf][rh * 2], d[mf][nf][rh * 2 + 1]);
            }
    __syncthreads();

    for (int i = 0; i < 16; i++) {
        int row = w * 16 + i;
        float x[4];
        float mx = -1e30f;
#pragma unroll
        for (int q = 0; q < 4; q++) {
            int v = lane + q * 32;
            x[q] = ep[row * EP_LD + v] + bout[v];
            mx = fmaxf(mx, x[q]);
        }
#pragma unroll
        for (int off = 16; off > 0; off >>= 1)
            mx = fmaxf(mx, __shfl_xor_sync(0xffffffffu, mx, off));
        float s = 0.f;
#pragma unroll
        for (int q = 0; q < 4; q++) s += expf(x[q] - mx);
#pragma unroll
        for (int off = 16; off > 0; off >>= 1)
            s += __shfl_xor_sync(0xffffffffu, s, off);
        float L = mx + logf(s);
        float* orow = out + (size_t)(m0 + row) * VOC;
#pragma unroll
        for (int q = 0; q < 4; q++) orow[lane + q * 32] = x[q] - L;
    }
}

__global__ void finalize_h(float* __restrict__ out) {
    float* dst = out + (size_t)TLEN * BSZ * VOC;
    const float* src = g_Hall + (size_t)TLEN * BSZ * HID;
    for (int i = blockIdx.x * blockDim.x + threadIdx.x; i < BSZ * HID;
         i += gridDim.x * blockDim.x)
        dst[i] = src[i];
}

// ---------------------------------------------------------------------------
extern "C" void kernel_launch(void* const* d_in, const int* in_sizes, int n_in,
                              void* d_out, int out_size) {
    (void)in_sizes; (void)n_in; (void)out_size;
    const float* enc_h = (const float*)d_in[1];
    const int*   tgt   = (const int*)d_in[2];
    const float* emb   = (const float*)d_in[3];
    const float* Wih   = (const float*)d_in[4];
    const float* Whh   = (const float*)d_in[5];
    const float* bih   = (const float*)d_in[6];
    const float* bhh   = (const float*)d_in[7];
    const float* Wout  = (const float*)d_in[8];
    const float* bout  = (const float*)d_in[9];
    float* out = (float*)d_out;

    const int log_smem = 2 * SBUF2 * 4;          // 71680 B
    cudaFuncSetAttribute(gru_persist, cudaFuncAttributeMaxDynamicSharedMemorySize, GRU_SMEM);
    cudaFuncSetAttribute(logits_all,  cudaFuncAttributeMaxDynamicSharedMemorySize, log_smem);

    prep_w <<<512, 256>>>(Whh, Wout);
    prep_gi<<<VOC, 256>>>(emb, Wih, bih, bhh);
    init_h <<<1024, 256>>>(enc_h);

    gru_persist<<<dim3(16, 16), 256, GRU_SMEM>>>(tgt);

    logits_all<<<(TLEN * BSZ) / 128, 256, log_smem>>>(bout, out);
    finalize_h<<<1024, 256>>>(out);
}